// round 2
// baseline (speedup 1.0000x reference)
#include <cuda_runtime.h>
#include <math.h>

// LinkPredictor fused kernel, fp32 baseline (round 1: fix edge_index dtype).
// Inputs (metadata order):
//   0: z          [500000*128] f32
//   1: edge_index [2*500000]   int32 (harness-converted from int64) OR int64
//   2: W1 [512*128] f32   3: b1 [128] f32
//   4: W2 [128*64]  f32   5: b2 [64]  f32
//   6: W3 [64]      f32   7: b3 [1]   f32
// Output: score [500000] f32

#define HDIM 128

constexpr int TM       = 64;    // edges per block
constexpr int THREADS  = 256;   // 8 warps * 8 edges each
constexpr int A_STRIDE = 520;   // 512 + 8 pad floats, rows 16B-aligned
constexpr int H_STRIDE = 132;   // 128 + 4 pad floats
constexpr int SMEM_FLOATS = TM * A_STRIDE + TM * H_STRIDE;  // 166912 B

// 1 => edge_index is int64, 0 => int32. Set by detect kernel each launch.
__device__ int g_ei_is64;

__global__ void detect_ei_dtype(const void* ei, int E, int n_nodes)
{
    const long long* e64 = (const long long*)ei;
    int n = (E < 64) ? E : 64;
    int is64 = 1;
    for (int i = 0; i < n; i++) {
        long long v = e64[i];
        if (v < 0 || v >= (long long)n_nodes) { is64 = 0; break; }
    }
    g_ei_is64 = is64;
}

__global__ __launch_bounds__(THREADS, 1)
void link_pred_kernel(const float* __restrict__ z,
                      const void* __restrict__ ei_raw,
                      const float* __restrict__ W1,
                      const float* __restrict__ b1,
                      const float* __restrict__ W2,
                      const float* __restrict__ b2,
                      const float* __restrict__ W3,
                      const float* __restrict__ b3,
                      float* __restrict__ out,
                      int E)
{
    extern __shared__ float smem[];
    float* As = smem;                        // [TM][A_STRIDE]
    float* Hs = smem + TM * A_STRIDE;        // [TM][H_STRIDE]

    const int tid  = threadIdx.x;
    const int warp = tid >> 5;
    const int lane = tid & 31;
    const int eb   = blockIdx.x * TM;
    const int m0   = warp * 8;               // this warp owns tile rows m0..m0+7

    const int is64 = g_ei_is64;
    const long long* e64 = (const long long*)ei_raw;
    const int*       e32 = (const int*)ei_raw;

    // ---------------- Phase 1: gather + build edge_repr tile ----------------
    #pragma unroll
    for (int i = 0; i < 8; i++) {
        const int eloc = m0 + i;
        int e = eb + eloc;
        const int ec = (e < E) ? e : (E - 1);    // clamp OOB (result discarded)

        long long s, d;
        if (is64) { s = e64[ec];            d = e64[(size_t)E + ec]; }
        else      { s = (long long)e32[ec]; d = (long long)e32[(size_t)E + ec]; }

        const float4 sv = *(const float4*)(z + (size_t)s * HDIM + lane * 4);
        const float4 dv = *(const float4*)(z + (size_t)d * HDIM + lane * 4);
        float4 iv, fv;
        iv.x = sv.x * dv.x; iv.y = sv.y * dv.y; iv.z = sv.z * dv.z; iv.w = sv.w * dv.w;
        fv.x = fabsf(sv.x - dv.x); fv.y = fabsf(sv.y - dv.y);
        fv.z = fabsf(sv.z - dv.z); fv.w = fabsf(sv.w - dv.w);

        float* row = As + eloc * A_STRIDE + lane * 4;
        *(float4*)(row +   0) = sv;
        *(float4*)(row + 128) = dv;
        *(float4*)(row + 256) = iv;
        *(float4*)(row + 384) = fv;
    }
    __syncwarp();   // tile rows are warp-private

    // ---------------- Phase 2: GEMM1  C1[64][128] = A[64][512] @ W1 ----------
    const int n0 = lane * 4;
    float acc[8][4];
    #pragma unroll
    for (int m = 0; m < 8; m++)
        #pragma unroll
        for (int n = 0; n < 4; n++) acc[m][n] = 0.0f;

    #pragma unroll 4
    for (int k = 0; k < 512; k += 4) {
        float bb[4][4];
        #pragma unroll
        for (int j = 0; j < 4; j++) {
            const float4 t = *(const float4*)(W1 + (k + j) * HDIM + n0);
            bb[j][0] = t.x; bb[j][1] = t.y; bb[j][2] = t.z; bb[j][3] = t.w;
        }
        #pragma unroll
        for (int m = 0; m < 8; m++) {
            const float4 a = *(const float4*)(As + (m0 + m) * A_STRIDE + k);
            #pragma unroll
            for (int n = 0; n < 4; n++) {
                acc[m][n] += a.x * bb[0][n];
                acc[m][n] += a.y * bb[1][n];
                acc[m][n] += a.z * bb[2][n];
                acc[m][n] += a.w * bb[3][n];
            }
        }
    }

    // bias + relu -> h1 tile in smem
    {
        const float4 bv = *(const float4*)(b1 + n0);
        #pragma unroll
        for (int m = 0; m < 8; m++) {
            float4 h;
            h.x = fmaxf(acc[m][0] + bv.x, 0.0f);
            h.y = fmaxf(acc[m][1] + bv.y, 0.0f);
            h.z = fmaxf(acc[m][2] + bv.z, 0.0f);
            h.w = fmaxf(acc[m][3] + bv.w, 0.0f);
            *(float4*)(Hs + (m0 + m) * H_STRIDE + n0) = h;
        }
    }
    __syncwarp();

    // ---------------- Phase 3: GEMM2  C2[64][64] = H1 @ W2 -------------------
    const int n2 = lane * 2;
    float acc2[8][2];
    #pragma unroll
    for (int m = 0; m < 8; m++) { acc2[m][0] = 0.0f; acc2[m][1] = 0.0f; }

    #pragma unroll 4
    for (int k = 0; k < 128; k += 4) {
        float b20[4], b21[4];
        #pragma unroll
        for (int j = 0; j < 4; j++) {
            const float2 t = *(const float2*)(W2 + (k + j) * 64 + n2);
            b20[j] = t.x; b21[j] = t.y;
        }
        #pragma unroll
        for (int m = 0; m < 8; m++) {
            const float4 a = *(const float4*)(Hs + (m0 + m) * H_STRIDE + k);
            acc2[m][0] += a.x * b20[0] + a.y * b20[1] + a.z * b20[2] + a.w * b20[3];
            acc2[m][1] += a.x * b21[0] + a.y * b21[1] + a.z * b21[2] + a.w * b21[3];
        }
    }

    // ---------------- Phase 4: bias+relu, GEMM3, warp reduction --------------
    const float2 b2v = *(const float2*)(b2 + n2);
    const float w3a = W3[n2];
    const float w3b = W3[n2 + 1];

    float p[8];
    #pragma unroll
    for (int m = 0; m < 8; m++) {
        const float h0  = fmaxf(acc2[m][0] + b2v.x, 0.0f);
        const float h1v = fmaxf(acc2[m][1] + b2v.y, 0.0f);
        p[m] = h0 * w3a + h1v * w3b;
    }

    #pragma unroll
    for (int off = 16; off > 0; off >>= 1) {
        #pragma unroll
        for (int m = 0; m < 8; m++)
            p[m] += __shfl_xor_sync(0xffffffff, p[m], off);
    }

    if (lane == 0) {
        const float bias3 = b3[0];
        #pragma unroll
        for (int m = 0; m < 8; m++) {
            const int e = eb + m0 + m;
            if (e < E) out[e] = p[m] + bias3;
        }
    }
}

extern "C" void kernel_launch(void* const* d_in, const int* in_sizes, int n_in,
                              void* d_out, int out_size)
{
    const float* z  = (const float*)d_in[0];
    const void*  ei = d_in[1];
    const float* W1 = (const float*)d_in[2];
    const float* b1 = (const float*)d_in[3];
    const float* W2 = (const float*)d_in[4];
    const float* b2 = (const float*)d_in[5];
    const float* W3 = (const float*)d_in[6];
    const float* b3 = (const float*)d_in[7];
    float* out = (float*)d_out;

    const int E = out_size;                 // one score per edge
    const int n_nodes = in_sizes[0] / HDIM;
    const int smem_bytes = SMEM_FLOATS * (int)sizeof(float);

    static bool attr_set = false;
    if (!attr_set) {
        cudaFuncSetAttribute(link_pred_kernel,
                             cudaFuncAttributeMaxDynamicSharedMemorySize, smem_bytes);
        attr_set = true;
    }

    detect_ei_dtype<<<1, 1>>>(ei, E, n_nodes);

    const int grid = (E + TM - 1) / TM;
    link_pred_kernel<<<grid, THREADS, smem_bytes>>>(z, ei, W1, b1, W2, b2, W3, b3, out, E);
}

// round 3
// speedup vs baseline: 1.0014x; 1.0014x over previous
#include <cuda_runtime.h>
#include <math.h>

// LinkPredictor fused kernel, fp32 baseline (round 1: fix edge_index dtype).
// Inputs (metadata order):
//   0: z          [500000*128] f32
//   1: edge_index [2*500000]   int32 (harness-converted from int64) OR int64
//   2: W1 [512*128] f32   3: b1 [128] f32
//   4: W2 [128*64]  f32   5: b2 [64]  f32
//   6: W3 [64]      f32   7: b3 [1]   f32
// Output: score [500000] f32

#define HDIM 128

constexpr int TM       = 64;    // edges per block
constexpr int THREADS  = 256;   // 8 warps * 8 edges each
constexpr int A_STRIDE = 520;   // 512 + 8 pad floats, rows 16B-aligned
constexpr int H_STRIDE = 132;   // 128 + 4 pad floats
constexpr int SMEM_FLOATS = TM * A_STRIDE + TM * H_STRIDE;  // 166912 B

// 1 => edge_index is int64, 0 => int32. Set by detect kernel each launch.
__device__ int g_ei_is64;

__global__ void detect_ei_dtype(const void* ei, int E, int n_nodes)
{
    const long long* e64 = (const long long*)ei;
    int n = (E < 64) ? E : 64;
    int is64 = 1;
    for (int i = 0; i < n; i++) {
        long long v = e64[i];
        if (v < 0 || v >= (long long)n_nodes) { is64 = 0; break; }
    }
    g_ei_is64 = is64;
}

__global__ __launch_bounds__(THREADS, 1)
void link_pred_kernel(const float* __restrict__ z,
                      const void* __restrict__ ei_raw,
                      const float* __restrict__ W1,
                      const float* __restrict__ b1,
                      const float* __restrict__ W2,
                      const float* __restrict__ b2,
                      const float* __restrict__ W3,
                      const float* __restrict__ b3,
                      float* __restrict__ out,
                      int E)
{
    extern __shared__ float smem[];
    float* As = smem;                        // [TM][A_STRIDE]
    float* Hs = smem + TM * A_STRIDE;        // [TM][H_STRIDE]

    const int tid  = threadIdx.x;
    const int warp = tid >> 5;
    const int lane = tid & 31;
    const int eb   = blockIdx.x * TM;
    const int m0   = warp * 8;               // this warp owns tile rows m0..m0+7

    const int is64 = g_ei_is64;
    const long long* e64 = (const long long*)ei_raw;
    const int*       e32 = (const int*)ei_raw;

    // ---------------- Phase 1: gather + build edge_repr tile ----------------
    #pragma unroll
    for (int i = 0; i < 8; i++) {
        const int eloc = m0 + i;
        int e = eb + eloc;
        const int ec = (e < E) ? e : (E - 1);    // clamp OOB (result discarded)

        long long s, d;
        if (is64) { s = e64[ec];            d = e64[(size_t)E + ec]; }
        else      { s = (long long)e32[ec]; d = (long long)e32[(size_t)E + ec]; }

        const float4 sv = *(const float4*)(z + (size_t)s * HDIM + lane * 4);
        const float4 dv = *(const float4*)(z + (size_t)d * HDIM + lane * 4);
        float4 iv, fv;
        iv.x = sv.x * dv.x; iv.y = sv.y * dv.y; iv.z = sv.z * dv.z; iv.w = sv.w * dv.w;
        fv.x = fabsf(sv.x - dv.x); fv.y = fabsf(sv.y - dv.y);
        fv.z = fabsf(sv.z - dv.z); fv.w = fabsf(sv.w - dv.w);

        float* row = As + eloc * A_STRIDE + lane * 4;
        *(float4*)(row +   0) = sv;
        *(float4*)(row + 128) = dv;
        *(float4*)(row + 256) = iv;
        *(float4*)(row + 384) = fv;
    }
    __syncwarp();   // tile rows are warp-private

    // ---------------- Phase 2: GEMM1  C1[64][128] = A[64][512] @ W1 ----------
    const int n0 = lane * 4;
    float acc[8][4];
    #pragma unroll
    for (int m = 0; m < 8; m++)
        #pragma unroll
        for (int n = 0; n < 4; n++) acc[m][n] = 0.0f;

    #pragma unroll 4
    for (int k = 0; k < 512; k += 4) {
        float bb[4][4];
        #pragma unroll
        for (int j = 0; j < 4; j++) {
            const float4 t = *(const float4*)(W1 + (k + j) * HDIM + n0);
            bb[j][0] = t.x; bb[j][1] = t.y; bb[j][2] = t.z; bb[j][3] = t.w;
        }
        #pragma unroll
        for (int m = 0; m < 8; m++) {
            const float4 a = *(const float4*)(As + (m0 + m) * A_STRIDE + k);
            #pragma unroll
            for (int n = 0; n < 4; n++) {
                acc[m][n] += a.x * bb[0][n];
                acc[m][n] += a.y * bb[1][n];
                acc[m][n] += a.z * bb[2][n];
                acc[m][n] += a.w * bb[3][n];
            }
        }
    }

    // bias + relu -> h1 tile in smem
    {
        const float4 bv = *(const float4*)(b1 + n0);
        #pragma unroll
        for (int m = 0; m < 8; m++) {
            float4 h;
            h.x = fmaxf(acc[m][0] + bv.x, 0.0f);
            h.y = fmaxf(acc[m][1] + bv.y, 0.0f);
            h.z = fmaxf(acc[m][2] + bv.z, 0.0f);
            h.w = fmaxf(acc[m][3] + bv.w, 0.0f);
            *(float4*)(Hs + (m0 + m) * H_STRIDE + n0) = h;
        }
    }
    __syncwarp();

    // ---------------- Phase 3: GEMM2  C2[64][64] = H1 @ W2 -------------------
    const int n2 = lane * 2;
    float acc2[8][2];
    #pragma unroll
    for (int m = 0; m < 8; m++) { acc2[m][0] = 0.0f; acc2[m][1] = 0.0f; }

    #pragma unroll 4
    for (int k = 0; k < 128; k += 4) {
        float b20[4], b21[4];
        #pragma unroll
        for (int j = 0; j < 4; j++) {
            const float2 t = *(const float2*)(W2 + (k + j) * 64 + n2);
            b20[j] = t.x; b21[j] = t.y;
        }
        #pragma unroll
        for (int m = 0; m < 8; m++) {
            const float4 a = *(const float4*)(Hs + (m0 + m) * H_STRIDE + k);
            acc2[m][0] += a.x * b20[0] + a.y * b20[1] + a.z * b20[2] + a.w * b20[3];
            acc2[m][1] += a.x * b21[0] + a.y * b21[1] + a.z * b21[2] + a.w * b21[3];
        }
    }

    // ---------------- Phase 4: bias+relu, GEMM3, warp reduction --------------
    const float2 b2v = *(const float2*)(b2 + n2);
    const float w3a = W3[n2];
    const float w3b = W3[n2 + 1];

    float p[8];
    #pragma unroll
    for (int m = 0; m < 8; m++) {
        const float h0  = fmaxf(acc2[m][0] + b2v.x, 0.0f);
        const float h1v = fmaxf(acc2[m][1] + b2v.y, 0.0f);
        p[m] = h0 * w3a + h1v * w3b;
    }

    #pragma unroll
    for (int off = 16; off > 0; off >>= 1) {
        #pragma unroll
        for (int m = 0; m < 8; m++)
            p[m] += __shfl_xor_sync(0xffffffff, p[m], off);
    }

    if (lane == 0) {
        const float bias3 = b3[0];
        #pragma unroll
        for (int m = 0; m < 8; m++) {
            const int e = eb + m0 + m;
            if (e < E) out[e] = p[m] + bias3;
        }
    }
}

extern "C" void kernel_launch(void* const* d_in, const int* in_sizes, int n_in,
                              void* d_out, int out_size)
{
    const float* z  = (const float*)d_in[0];
    const void*  ei = d_in[1];
    const float* W1 = (const float*)d_in[2];
    const float* b1 = (const float*)d_in[3];
    const float* W2 = (const float*)d_in[4];
    const float* b2 = (const float*)d_in[5];
    const float* W3 = (const float*)d_in[6];
    const float* b3 = (const float*)d_in[7];
    float* out = (float*)d_out;

    const int E = out_size;                 // one score per edge
    const int n_nodes = in_sizes[0] / HDIM;
    const int smem_bytes = SMEM_FLOATS * (int)sizeof(float);

    static bool attr_set = false;
    if (!attr_set) {
        cudaFuncSetAttribute(link_pred_kernel,
                             cudaFuncAttributeMaxDynamicSharedMemorySize, smem_bytes);
        attr_set = true;
    }

    detect_ei_dtype<<<1, 1>>>(ei, E, n_nodes);

    const int grid = (E + TM - 1) / TM;
    link_pred_kernel<<<grid, THREADS, smem_bytes>>>(z, ei, W1, b1, W2, b2, W3, b3, out, E);
}

// round 5
// speedup vs baseline: 2.0495x; 2.0467x over previous
#include <cuda_runtime.h>
#include <cuda_bf16.h>
#include <cstdint>
#include <math.h>

// LinkPredictor via mma.sync (HMMA bf16, 2-term split, fp32 accum).
// Valid at compute_103 (no sm_103a-only instructions).
// Inputs: 0:z[500000*128]f32 1:edge_index[2*E] (i32 or i64)
//         2:W1[512*128] 3:b1[128] 4:W2[128*64] 5:b2[64] 6:W3[64] 7:b3[1]
// Output: score[E] f32

#define HDIM 128
constexpr int MB      = 64;     // edges per block
constexpr int THREADS = 256;    // 8 warps

// ---- smem layout (bytes) ----
constexpr int OFF_PART  = 0;        // 512 B reduction scratch
constexpr int PLANE     = 16384;    // 64 rows * 256 B
constexpr int OFF_SRC_H = 1024;
constexpr int OFF_SRC_L = OFF_SRC_H + PLANE;
constexpr int OFF_DST_H = OFF_SRC_L + PLANE;
constexpr int OFF_DST_L = OFF_DST_H + PLANE;
constexpr int OFF_A23_H = OFF_DST_L + PLANE;      // chunk2/3, later h1
constexpr int OFF_A23_L = OFF_A23_H + PLANE;
constexpr int OFF_W0    = OFF_A23_L + PLANE;      // 99328
constexpr int OFF_W1B   = OFF_W0 + 65536;         // 164864
constexpr int SMEM_TOTAL = OFF_W1B + 65536;       // 230400 <= 232448

// preconverted, pre-swizzled weights
__device__ unsigned char g_W1p[4 * 65536];  // [chunk][hi 32K | lo 32K], rows=n(128),k=128
__device__ unsigned char g_W2p[32768];      // [hi 16K | lo 16K], rows=n(64),k=128
__device__ int g_ei_is64;

// ---- helpers ----
__device__ __forceinline__ uint32_t smem_u32(const void* p) {
    uint32_t a;
    asm("{ .reg .u64 t; cvta.to.shared.u64 t, %1; cvt.u32.u64 %0, t; }" : "=r"(a) : "l"(p));
    return a;
}
__device__ __forceinline__ void ldsm4(uint32_t& r0, uint32_t& r1, uint32_t& r2, uint32_t& r3,
                                      uint32_t addr) {
    asm volatile("ldmatrix.sync.aligned.m8n8.x4.shared.b16 {%0,%1,%2,%3}, [%4];"
        : "=r"(r0), "=r"(r1), "=r"(r2), "=r"(r3) : "r"(addr));
}
__device__ __forceinline__ void mma16816(float* c, uint32_t a0, uint32_t a1, uint32_t a2,
                                         uint32_t a3, uint32_t b0, uint32_t b1) {
    asm volatile("mma.sync.aligned.m16n8k16.row.col.f32.bf16.bf16.f32 "
        "{%0,%1,%2,%3}, {%4,%5,%6,%7}, {%8,%9}, {%0,%1,%2,%3};"
        : "+f"(c[0]), "+f"(c[1]), "+f"(c[2]), "+f"(c[3])
        : "r"(a0), "r"(a1), "r"(a2), "r"(a3), "r"(b0), "r"(b1));
}
__device__ __forceinline__ void cp16(uint32_t dst, const void* src) {
    asm volatile("cp.async.cg.shared.global [%0], [%1], 16;" :: "r"(dst), "l"(src));
}
#define CP_COMMIT() asm volatile("cp.async.commit_group;" ::: "memory")
template <int N> __device__ __forceinline__ void cp_wait() {
    asm volatile("cp.async.wait_group %0;" :: "n"(N) : "memory");
}

// swizzled offset within a plane: row stride 256B, 16B units XORed by row&7
__device__ __host__ __forceinline__ uint32_t aoff(int row, int k) {
    return (uint32_t)(row * 256 + (((k >> 3) ^ (row & 7)) << 4) + (k & 7) * 2);
}
__device__ __forceinline__ void bsplit(float f, uint16_t& h, uint16_t& l) {
    __nv_bfloat16 hb = __float2bfloat16(f);
    h = __bfloat16_as_ushort(hb);
    l = __bfloat16_as_ushort(__float2bfloat16(f - __bfloat162float(hb)));
}
__device__ __forceinline__ void split4_pack(float4 v, uint2& hi, uint2& lo) {
    uint16_t h0, h1, h2, h3, l0, l1, l2, l3;
    bsplit(v.x, h0, l0); bsplit(v.y, h1, l1);
    bsplit(v.z, h2, l2); bsplit(v.w, h3, l3);
    hi.x = (uint32_t)h0 | ((uint32_t)h1 << 16);
    hi.y = (uint32_t)h2 | ((uint32_t)h3 << 16);
    lo.x = (uint32_t)l0 | ((uint32_t)l1 << 16);
    lo.y = (uint32_t)l2 | ((uint32_t)l3 << 16);
}
__device__ __forceinline__ float bfr(uint32_t w, int hi16) {
    return __bfloat162float(__ushort_as_bfloat16((uint16_t)(hi16 ? (w >> 16) : (w & 0xffff))));
}

// ---- setup kernels ----
__global__ void detect_ei_dtype(const void* ei, int E, int n_nodes) {
    const long long* e64 = (const long long*)ei;
    int n = (E < 64) ? E : 64;
    int is64 = 1;
    for (int i = 0; i < n; i++) {
        long long v = e64[i];
        if (v < 0 || v >= (long long)n_nodes) { is64 = 0; break; }
    }
    g_ei_is64 = is64;
}

__global__ void prep_weights(const float* __restrict__ W1, const float* __restrict__ W2) {
    int idx = blockIdx.x * 256 + threadIdx.x;
    if (idx < 65536) {                       // W1[512][128]: B[n][k] = W1[c*128+k][n]
        int c = idx >> 14, e = idx & 16383;
        int n = e >> 7, k = e & 127;
        float f = W1[(c * 128 + k) * 128 + n];
        uint16_t hi, lo; bsplit(f, hi, lo);
        unsigned char* base = g_W1p + (size_t)c * 65536;
        uint32_t o = aoff(n, k);
        *(uint16_t*)(base + o)         = hi;
        *(uint16_t*)(base + 32768 + o) = lo;
    } else if (idx < 65536 + 8192) {         // W2[128][64]: B[n][k] = W2[k][n]
        int e = idx - 65536;
        int n = e >> 7, k = e & 127;
        float f = W2[k * 64 + n];
        uint16_t hi, lo; bsplit(f, hi, lo);
        uint32_t o = aoff(n, k);
        *(uint16_t*)(g_W2p + o)         = hi;
        *(uint16_t*)(g_W2p + 16384 + o) = lo;
    }
}

// ---- main kernel ----
__global__ __launch_bounds__(THREADS, 1)
void lp_main(const float* __restrict__ z,
             const void* __restrict__ ei_raw,
             const float* __restrict__ b1,
             const float* __restrict__ b2,
             const float* __restrict__ W3,
             const float* __restrict__ b3,
             float* __restrict__ out,
             int E)
{
    extern __shared__ unsigned char sm[];
    const uint32_t smb = smem_u32(sm);
    const int tid  = threadIdx.x;
    const int warp = tid >> 5;
    const int lane = tid & 31;
    const int wm = warp >> 1, wn = warp & 1;
    const int m0 = wm * 16;
    const int eb = blockIdx.x * MB;

    // prefetch W1 chunk 0 -> wbuf0
    {
        const unsigned char* src = g_W1p;
        #pragma unroll
        for (int t = 0; t < 16; t++) {
            uint32_t o = (uint32_t)(tid + t * 256) * 16;
            cp16(smb + OFF_W0 + o, src + o);
        }
        CP_COMMIT();
    }

    // ---- gather: build src/dst hi/lo planes + chunk2 (src*dst) ----
    {
        const int is64 = g_ei_is64;
        const long long* e64 = (const long long*)ei_raw;
        const int*       e32 = (const int*)ei_raw;
        #pragma unroll 2
        for (int i = 0; i < 8; i++) {
            const int r = warp * 8 + i;
            const int e = eb + r;
            const int ec = (e < E) ? e : (E - 1);
            long long s, d;
            if (is64) { s = e64[ec]; d = e64[(size_t)E + ec]; }
            else      { s = (long long)e32[ec]; d = (long long)e32[(size_t)E + ec]; }

            const float4 sv = *(const float4*)(z + (size_t)s * HDIM + lane * 4);
            const float4 dv = *(const float4*)(z + (size_t)d * HDIM + lane * 4);
            float4 iv;
            iv.x = sv.x * dv.x; iv.y = sv.y * dv.y; iv.z = sv.z * dv.z; iv.w = sv.w * dv.w;

            const uint32_t o = aoff(r, lane * 4);
            uint2 hi, lo;
            split4_pack(sv, hi, lo);
            *(uint2*)(sm + OFF_SRC_H + o) = hi;  *(uint2*)(sm + OFF_SRC_L + o) = lo;
            split4_pack(dv, hi, lo);
            *(uint2*)(sm + OFF_DST_H + o) = hi;  *(uint2*)(sm + OFF_DST_L + o) = lo;
            split4_pack(iv, hi, lo);
            *(uint2*)(sm + OFF_A23_H + o) = hi;  *(uint2*)(sm + OFF_A23_L + o) = lo;
        }
    }

    // ---- per-thread ldmatrix geometry ----
    const int tileA = lane >> 3;
    const int rowA  = m0 + ((tileA & 1) << 3) + (lane & 7);
    const int rxA   = rowA & 7;
    const int kuA   = tileA >> 1;            // 0 or 1 (k unit offset)
    const int kuB   = (lane >> 3) & 1;
    int rowB[4], rxB[4];
    {
        const int nb = wn * 64;
        #pragma unroll
        for (int jp = 0; jp < 4; jp++) {
            rowB[jp] = nb + jp * 16 + ((lane >> 4) << 3) + (lane & 7);
            rxB[jp]  = rowB[jp] & 7;
        }
    }

    float acc[32];
    #pragma unroll
    for (int i = 0; i < 32; i++) acc[i] = 0.0f;

    static const int AH[4] = {OFF_SRC_H, OFF_DST_H, OFF_A23_H, OFF_A23_H};
    static const int AL[4] = {OFF_SRC_L, OFF_DST_L, OFF_A23_L, OFF_A23_L};

    // ---- GEMM1: 4 K-chunks of 128 ----
    #pragma unroll 1
    for (int c = 0; c < 4; c++) {
        __syncthreads();     // prev chunk's smem reads complete

        if (c == 3) {        // rebuild A23 = |src-dst| from 16-bit planes
            #pragma unroll
            for (int t = 0; t < 8; t++) {
                const int idx = tid + t * 256;      // 2048 items of 4 cols
                const int r = idx >> 5, kg = (idx & 31) * 4;
                const uint32_t o = aoff(r, kg);
                const uint2 shv = *(const uint2*)(sm + OFF_SRC_H + o);
                const uint2 slv = *(const uint2*)(sm + OFF_SRC_L + o);
                const uint2 dhv = *(const uint2*)(sm + OFF_DST_H + o);
                const uint2 dlv = *(const uint2*)(sm + OFF_DST_L + o);
                float4 v;
                v.x = fabsf((bfr(shv.x,0)+bfr(slv.x,0)) - (bfr(dhv.x,0)+bfr(dlv.x,0)));
                v.y = fabsf((bfr(shv.x,1)+bfr(slv.x,1)) - (bfr(dhv.x,1)+bfr(dlv.x,1)));
                v.z = fabsf((bfr(shv.y,0)+bfr(slv.y,0)) - (bfr(dhv.y,0)+bfr(dlv.y,0)));
                v.w = fabsf((bfr(shv.y,1)+bfr(slv.y,1)) - (bfr(dhv.y,1)+bfr(dlv.y,1)));
                uint2 hi, lo; split4_pack(v, hi, lo);
                *(uint2*)(sm + OFF_A23_H + o) = hi;
                *(uint2*)(sm + OFF_A23_L + o) = lo;
            }
        }

        // prefetch next W block into the other buffer
        if (c < 3) {
            const unsigned char* src = g_W1p + (size_t)(c + 1) * 65536;
            const uint32_t dst = smb + (((c + 1) & 1) ? OFF_W1B : OFF_W0);
            #pragma unroll
            for (int t = 0; t < 16; t++) {
                uint32_t o = (uint32_t)(tid + t * 256) * 16;
                cp16(dst + o, src + o);
            }
        } else {
            #pragma unroll
            for (int t = 0; t < 8; t++) {
                uint32_t o = (uint32_t)(tid + t * 256) * 16;
                cp16(smb + OFF_W0 + o, g_W2p + o);
            }
        }
        CP_COMMIT();
        cp_wait<1>();        // current chunk's W resident
        __syncthreads();

        const uint32_t ahb = smb + AH[c] + rowA * 256;
        const uint32_t alb = smb + AL[c] + rowA * 256;
        const uint32_t wb  = smb + ((c & 1) ? OFF_W1B : OFF_W0);
        uint32_t whb[4];
        #pragma unroll
        for (int jp = 0; jp < 4; jp++) whb[jp] = wb + rowB[jp] * 256;

        #pragma unroll
        for (int ks = 0; ks < 8; ks++) {
            const int kq = ks * 2;
            uint32_t a0, a1, a2, a3, l0, l1, l2, l3;
            const uint32_t ao = (uint32_t)((kq + kuA) ^ rxA) << 4;
            ldsm4(a0, a1, a2, a3, ahb + ao);
            ldsm4(l0, l1, l2, l3, alb + ao);
            uint32_t bh[16], bl[16];
            #pragma unroll
            for (int jp = 0; jp < 4; jp++) {
                const uint32_t bo = (uint32_t)((kq + kuB) ^ rxB[jp]) << 4;
                ldsm4(bh[4*jp], bh[4*jp+1], bh[4*jp+2], bh[4*jp+3], whb[jp] + bo);
                ldsm4(bl[4*jp], bl[4*jp+1], bl[4*jp+2], bl[4*jp+3], whb[jp] + 32768 + bo);
            }
            #pragma unroll
            for (int j = 0; j < 8; j++)
                mma16816(&acc[4*j], a0, a1, a2, a3, bh[2*j], bh[2*j+1]);
            #pragma unroll
            for (int j = 0; j < 8; j++)
                mma16816(&acc[4*j], l0, l1, l2, l3, bh[2*j], bh[2*j+1]);
            #pragma unroll
            for (int j = 0; j < 8; j++)
                mma16816(&acc[4*j], a0, a1, a2, a3, bl[2*j], bl[2*j+1]);
        }
    }

    // ---- epilogue1: h1 = relu(C1 + b1) -> bf16 hi/lo into A23 planes ----
    __syncthreads();   // GEMM1 reads of A23 complete
    {
        const int r1 = m0 + (lane >> 2);
        #pragma unroll
        for (int j = 0; j < 8; j++) {
            const int col = wn * 64 + j * 8 + (lane & 3) * 2;
            const float ba = __ldg(b1 + col), bb = __ldg(b1 + col + 1);
            float v00 = fmaxf(acc[4*j]   + ba, 0.0f);
            float v01 = fmaxf(acc[4*j+1] + bb, 0.0f);
            float v10 = fmaxf(acc[4*j+2] + ba, 0.0f);
            float v11 = fmaxf(acc[4*j+3] + bb, 0.0f);
            uint16_t h0, h1v, l0v, l1v;
            const uint32_t o1 = aoff(r1, col), o2 = aoff(r1 + 8, col);
            bsplit(v00, h0, l0v); bsplit(v01, h1v, l1v);
            *(uint32_t*)(sm + OFF_A23_H + o1) = (uint32_t)h0 | ((uint32_t)h1v << 16);
            *(uint32_t*)(sm + OFF_A23_L + o1) = (uint32_t)l0v | ((uint32_t)l1v << 16);
            bsplit(v10, h0, l0v); bsplit(v11, h1v, l1v);
            *(uint32_t*)(sm + OFF_A23_H + o2) = (uint32_t)h0 | ((uint32_t)h1v << 16);
            *(uint32_t*)(sm + OFF_A23_L + o2) = (uint32_t)l0v | ((uint32_t)l1v << 16);
        }
    }
    cp_wait<0>();       // W2 resident
    __syncthreads();

    // ---- GEMM2: C2[64][64] = h1 @ W2 ----
    float acc2[16];
    #pragma unroll
    for (int i = 0; i < 16; i++) acc2[i] = 0.0f;
    {
        const uint32_t ahb = smb + OFF_A23_H + rowA * 256;
        const uint32_t alb = smb + OFF_A23_L + rowA * 256;
        int rowB2[2], rxB2[2];
        #pragma unroll
        for (int jp = 0; jp < 2; jp++) {
            rowB2[jp] = wn * 32 + jp * 16 + ((lane >> 4) << 3) + (lane & 7);
            rxB2[jp]  = rowB2[jp] & 7;
        }
        #pragma unroll
        for (int ks = 0; ks < 8; ks++) {
            const int kq = ks * 2;
            uint32_t a0, a1, a2, a3, l0, l1, l2, l3;
            const uint32_t ao = (uint32_t)((kq + kuA) ^ rxA) << 4;
            ldsm4(a0, a1, a2, a3, ahb + ao);
            ldsm4(l0, l1, l2, l3, alb + ao);
            uint32_t bh[8], bl[8];
            #pragma unroll
            for (int jp = 0; jp < 2; jp++) {
                const uint32_t wbase = smb + OFF_W0 + rowB2[jp] * 256;
                const uint32_t bo = (uint32_t)((kq + kuB) ^ rxB2[jp]) << 4;
                ldsm4(bh[4*jp], bh[4*jp+1], bh[4*jp+2], bh[4*jp+3], wbase + bo);
                ldsm4(bl[4*jp], bl[4*jp+1], bl[4*jp+2], bl[4*jp+3], wbase + 16384 + bo);
            }
            #pragma unroll
            for (int j = 0; j < 4; j++)
                mma16816(&acc2[4*j], a0, a1, a2, a3, bh[2*j], bh[2*j+1]);
            #pragma unroll
            for (int j = 0; j < 4; j++)
                mma16816(&acc2[4*j], l0, l1, l2, l3, bh[2*j], bh[2*j+1]);
            #pragma unroll
            for (int j = 0; j < 4; j++)
                mma16816(&acc2[4*j], a0, a1, a2, a3, bl[2*j], bl[2*j+1]);
        }
    }

    // ---- epilogue2: score = relu(C2 + b2) . W3 (+b3) ----
    {
        float p1 = 0.0f, p2 = 0.0f;
        #pragma unroll
        for (int j = 0; j < 4; j++) {
            const int col = wn * 32 + j * 8 + (lane & 3) * 2;
            const float ba = __ldg(b2 + col), bb = __ldg(b2 + col + 1);
            const float wa = __ldg(W3 + col), wwb = __ldg(W3 + col + 1);
            p1 += fmaxf(acc2[4*j]   + ba, 0.0f) * wa;
            p1 += fmaxf(acc2[4*j+1] + bb, 0.0f) * wwb;
            p2 += fmaxf(acc2[4*j+2] + ba, 0.0f) * wa;
            p2 += fmaxf(acc2[4*j+3] + bb, 0.0f) * wwb;
        }
        p1 += __shfl_xor_sync(0xffffffff, p1, 1);
        p1 += __shfl_xor_sync(0xffffffff, p1, 2);
        p2 += __shfl_xor_sync(0xffffffff, p2, 1);
        p2 += __shfl_xor_sync(0xffffffff, p2, 2);
        float* part = (float*)(sm + OFF_PART);
        if ((lane & 3) == 0) {
            const int r1 = m0 + (lane >> 2);
            part[wn * 64 + r1]     = p1;
            part[wn * 64 + r1 + 8] = p2;
        }
    }
    __syncthreads();
    if (tid < MB) {
        const float* part = (const float*)(sm + OFF_PART);
        const int e = eb + tid;
        if (e < E) out[e] = part[tid] + part[64 + tid] + __ldg(b3);
    }
}

// ---- launcher ----
extern "C" void kernel_launch(void* const* d_in, const int* in_sizes, int n_in,
                              void* d_out, int out_size)
{
    const float* z  = (const float*)d_in[0];
    const void*  ei = d_in[1];
    const float* W1 = (const float*)d_in[2];
    const float* b1 = (const float*)d_in[3];
    const float* W2 = (const float*)d_in[4];
    const float* b2 = (const float*)d_in[5];
    const float* W3 = (const float*)d_in[6];
    const float* b3 = (const float*)d_in[7];
    float* out = (float*)d_out;

    const int E = out_size;
    const int n_nodes = in_sizes[0] / HDIM;

    static bool attr_set = false;
    if (!attr_set) {
        cudaFuncSetAttribute(lp_main, cudaFuncAttributeMaxDynamicSharedMemorySize, SMEM_TOTAL);
        attr_set = true;
    }

    detect_ei_dtype<<<1, 1>>>(ei, E, n_nodes);
    prep_weights<<<288, 256>>>(W1, W2);

    const int grid = (E + MB - 1) / MB;
    lp_main<<<grid, THREADS, SMEM_TOTAL>>>(z, ei, b1, b2, W3, b3, out, E);
}

// round 6
// speedup vs baseline: 2.6127x; 1.2748x over previous
#include <cuda_runtime.h>
#include <cuda_fp16.h>
#include <cstdint>
#include <math.h>

// LinkPredictor via mma.sync (HMMA fp16, A 2-term split, B single fp16, fp32 accum).
// Valid at compute_103. 2 MMA passes instead of 3 (error ~2.8e-4 << 1e-3).
// Inputs: 0:z[500000*128]f32 1:edge_index[2*E] (i32 or i64)
//         2:W1[512*128] 3:b1[128] 4:W2[128*64] 5:b2[64] 6:W3[64] 7:b3[1]
// Output: score[E] f32

#define HDIM 128
constexpr int MB      = 64;     // edges per block
constexpr int THREADS = 256;    // 8 warps

// ---- smem layout (bytes) ----
constexpr int OFF_PART  = 0;        // 512 B reduction scratch
constexpr int PLANE     = 16384;    // 64 rows * 256 B
constexpr int OFF_SRC_H = 1024;
constexpr int OFF_SRC_L = OFF_SRC_H + PLANE;
constexpr int OFF_DST_H = OFF_SRC_L + PLANE;
constexpr int OFF_DST_L = OFF_DST_H + PLANE;
constexpr int OFF_A23_H = OFF_DST_L + PLANE;      // chunk2/3, later h1
constexpr int OFF_A23_L = OFF_A23_H + PLANE;
constexpr int OFF_W0    = OFF_A23_L + PLANE;      // 99328  (32 KB buf)
constexpr int OFF_W1B   = OFF_W0 + 32768;         // 132096 (32 KB buf)
constexpr int SMEM_TOTAL = OFF_W1B + 32768;       // 164864

// preconverted, pre-swizzled weights (single fp16)
__device__ unsigned char g_W1p[4 * 32768];  // [chunk][n=128 rows][k=128 fp16]
__device__ unsigned char g_W2p[16384];      // [n=64 rows][k=128 fp16]
__device__ int g_ei_is64;

// ---- helpers ----
__device__ __forceinline__ uint32_t smem_u32(const void* p) {
    uint32_t a;
    asm("{ .reg .u64 t; cvta.to.shared.u64 t, %1; cvt.u32.u64 %0, t; }" : "=r"(a) : "l"(p));
    return a;
}
__device__ __forceinline__ void ldsm4(uint32_t& r0, uint32_t& r1, uint32_t& r2, uint32_t& r3,
                                      uint32_t addr) {
    asm volatile("ldmatrix.sync.aligned.m8n8.x4.shared.b16 {%0,%1,%2,%3}, [%4];"
        : "=r"(r0), "=r"(r1), "=r"(r2), "=r"(r3) : "r"(addr));
}
__device__ __forceinline__ void mma16816(float* c, uint32_t a0, uint32_t a1, uint32_t a2,
                                         uint32_t a3, uint32_t b0, uint32_t b1) {
    asm volatile("mma.sync.aligned.m16n8k16.row.col.f32.f16.f16.f32 "
        "{%0,%1,%2,%3}, {%4,%5,%6,%7}, {%8,%9}, {%0,%1,%2,%3};"
        : "+f"(c[0]), "+f"(c[1]), "+f"(c[2]), "+f"(c[3])
        : "r"(a0), "r"(a1), "r"(a2), "r"(a3), "r"(b0), "r"(b1));
}
__device__ __forceinline__ void cp16(uint32_t dst, const void* src) {
    asm volatile("cp.async.cg.shared.global [%0], [%1], 16;" :: "r"(dst), "l"(src));
}
#define CP_COMMIT() asm volatile("cp.async.commit_group;" ::: "memory")
template <int N> __device__ __forceinline__ void cp_wait() {
    asm volatile("cp.async.wait_group %0;" :: "n"(N) : "memory");
}

// swizzled offset within a plane: row stride 256B, 16B units XORed by row&7
__device__ __host__ __forceinline__ uint32_t aoff(int row, int k) {
    return (uint32_t)(row * 256 + (((k >> 3) ^ (row & 7)) << 4) + (k & 7) * 2);
}
__device__ __forceinline__ void hsplit(float f, uint16_t& h, uint16_t& l) {
    __half hh = __float2half_rn(f);
    h = __half_as_ushort(hh);
    l = __half_as_ushort(__float2half_rn(f - __half2float(hh)));
}
__device__ __forceinline__ void split4_pack(float4 v, uint2& hi, uint2& lo) {
    uint16_t h0, h1, h2, h3, l0, l1, l2, l3;
    hsplit(v.x, h0, l0); hsplit(v.y, h1, l1);
    hsplit(v.z, h2, l2); hsplit(v.w, h3, l3);
    hi.x = (uint32_t)h0 | ((uint32_t)h1 << 16);
    hi.y = (uint32_t)h2 | ((uint32_t)h3 << 16);
    lo.x = (uint32_t)l0 | ((uint32_t)l1 << 16);
    lo.y = (uint32_t)l2 | ((uint32_t)l3 << 16);
}
__device__ __forceinline__ float hfr(uint32_t w, int hi16) {
    return __half2float(__ushort_as_half((uint16_t)(hi16 ? (w >> 16) : (w & 0xffff))));
}

// ---- setup kernels ----
__global__ void detect_ei_dtype(const void* ei, int E, int n_nodes) {
    const long long* e64 = (const long long*)ei;
    int n = (E < 64) ? E : 64;
    int is64 = 1;
    for (int i = 0; i < n; i++) {
        long long v = e64[i];
        if (v < 0 || v >= (long long)n_nodes) { is64 = 0; break; }
    }
    g_ei_is64 = is64;
}

__global__ void prep_weights(const float* __restrict__ W1, const float* __restrict__ W2) {
    int idx = blockIdx.x * 256 + threadIdx.x;
    if (idx < 65536) {                       // W1[512][128]: B[n][k] = W1[c*128+k][n]
        int c = idx >> 14, e = idx & 16383;
        int n = e >> 7, k = e & 127;
        float f = W1[(c * 128 + k) * 128 + n];
        *(uint16_t*)(g_W1p + (size_t)c * 32768 + aoff(n, k)) =
            __half_as_ushort(__float2half_rn(f));
    } else if (idx < 65536 + 8192) {         // W2[128][64]: B[n][k] = W2[k][n]
        int e = idx - 65536;
        int n = e >> 7, k = e & 127;
        *(uint16_t*)(g_W2p + aoff(n, k)) =
            __half_as_ushort(__float2half_rn(W2[k * 64 + n]));
    }
}

// ---- main kernel ----
__global__ __launch_bounds__(THREADS, 1)
void lp_main(const float* __restrict__ z,
             const void* __restrict__ ei_raw,
             const float* __restrict__ b1,
             const float* __restrict__ b2,
             const float* __restrict__ W3,
             const float* __restrict__ b3,
             float* __restrict__ out,
             int E)
{
    extern __shared__ unsigned char sm[];
    const uint32_t smb = smem_u32(sm);
    const int tid  = threadIdx.x;
    const int warp = tid >> 5;
    const int lane = tid & 31;
    const int wm = warp >> 1, wn = warp & 1;
    const int m0 = wm * 16;
    const int eb = blockIdx.x * MB;

    // prefetch W1 chunk 0 -> wbuf0 (32 KB)
    {
        #pragma unroll
        for (int t = 0; t < 8; t++) {
            uint32_t o = (uint32_t)(tid + t * 256) * 16;
            cp16(smb + OFF_W0 + o, g_W1p + o);
        }
        CP_COMMIT();
    }

    // ---- gather: build src/dst hi/lo planes + chunk2 (src*dst) ----
    {
        const int is64 = g_ei_is64;
        const long long* e64 = (const long long*)ei_raw;
        const int*       e32 = (const int*)ei_raw;
        #pragma unroll 2
        for (int i = 0; i < 8; i++) {
            const int r = warp * 8 + i;
            const int e = eb + r;
            const int ec = (e < E) ? e : (E - 1);
            long long s, d;
            if (is64) { s = e64[ec]; d = e64[(size_t)E + ec]; }
            else      { s = (long long)e32[ec]; d = (long long)e32[(size_t)E + ec]; }

            const float4 sv = *(const float4*)(z + (size_t)s * HDIM + lane * 4);
            const float4 dv = *(const float4*)(z + (size_t)d * HDIM + lane * 4);
            float4 iv;
            iv.x = sv.x * dv.x; iv.y = sv.y * dv.y; iv.z = sv.z * dv.z; iv.w = sv.w * dv.w;

            const uint32_t o = aoff(r, lane * 4);
            uint2 hi, lo;
            split4_pack(sv, hi, lo);
            *(uint2*)(sm + OFF_SRC_H + o) = hi;  *(uint2*)(sm + OFF_SRC_L + o) = lo;
            split4_pack(dv, hi, lo);
            *(uint2*)(sm + OFF_DST_H + o) = hi;  *(uint2*)(sm + OFF_DST_L + o) = lo;
            split4_pack(iv, hi, lo);
            *(uint2*)(sm + OFF_A23_H + o) = hi;  *(uint2*)(sm + OFF_A23_L + o) = lo;
        }
    }

    // ---- per-thread ldmatrix geometry ----
    const int tileA = lane >> 3;
    const int rowA  = m0 + ((tileA & 1) << 3) + (lane & 7);
    const int rxA   = rowA & 7;
    const int kuA   = tileA >> 1;            // 0 or 1 (k unit offset)
    const int kuB   = (lane >> 3) & 1;
    int rowB[4], rxB[4];
    {
        const int nb = wn * 64;
        #pragma unroll
        for (int jp = 0; jp < 4; jp++) {
            rowB[jp] = nb + jp * 16 + ((lane >> 4) << 3) + (lane & 7);
            rxB[jp]  = rowB[jp] & 7;
        }
    }

    float acc[32];
    #pragma unroll
    for (int i = 0; i < 32; i++) acc[i] = 0.0f;

    static const int AH[4] = {OFF_SRC_H, OFF_DST_H, OFF_A23_H, OFF_A23_H};
    static const int AL[4] = {OFF_SRC_L, OFF_DST_L, OFF_A23_L, OFF_A23_L};

    // ---- GEMM1: 4 K-chunks of 128 ----
    #pragma unroll 1
    for (int c = 0; c < 4; c++) {
        __syncthreads();     // prev chunk's smem reads complete

        if (c == 3) {        // rebuild A23 = |src-dst| from hi/lo planes
            #pragma unroll
            for (int t = 0; t < 8; t++) {
                const int idx = tid + t * 256;      // 2048 items of 4 cols
                const int r = idx >> 5, kg = (idx & 31) * 4;
                const uint32_t o = aoff(r, kg);
                const uint2 shv = *(const uint2*)(sm + OFF_SRC_H + o);
                const uint2 slv = *(const uint2*)(sm + OFF_SRC_L + o);
                const uint2 dhv = *(const uint2*)(sm + OFF_DST_H + o);
                const uint2 dlv = *(const uint2*)(sm + OFF_DST_L + o);
                float4 v;
                v.x = fabsf((hfr(shv.x,0)+hfr(slv.x,0)) - (hfr(dhv.x,0)+hfr(dlv.x,0)));
                v.y = fabsf((hfr(shv.x,1)+hfr(slv.x,1)) - (hfr(dhv.x,1)+hfr(dlv.x,1)));
                v.z = fabsf((hfr(shv.y,0)+hfr(slv.y,0)) - (hfr(dhv.y,0)+hfr(dlv.y,0)));
                v.w = fabsf((hfr(shv.y,1)+hfr(slv.y,1)) - (hfr(dhv.y,1)+hfr(dlv.y,1)));
                uint2 hi, lo; split4_pack(v, hi, lo);
                *(uint2*)(sm + OFF_A23_H + o) = hi;
                *(uint2*)(sm + OFF_A23_L + o) = lo;
            }
        }

        // prefetch next W block into the other buffer
        if (c < 3) {
            const unsigned char* src = g_W1p + (size_t)(c + 1) * 32768;
            const uint32_t dst = smb + (((c + 1) & 1) ? OFF_W1B : OFF_W0);
            #pragma unroll
            for (int t = 0; t < 8; t++) {
                uint32_t o = (uint32_t)(tid + t * 256) * 16;
                cp16(dst + o, src + o);
            }
        } else {
            #pragma unroll
            for (int t = 0; t < 4; t++) {
                uint32_t o = (uint32_t)(tid + t * 256) * 16;
                cp16(smb + OFF_W0 + o, g_W2p + o);
            }
        }
        CP_COMMIT();
        cp_wait<1>();        // current chunk's W resident
        __syncthreads();

        const uint32_t ahb = smb + AH[c] + rowA * 256;
        const uint32_t alb = smb + AL[c] + rowA * 256;
        const uint32_t wb  = smb + ((c & 1) ? OFF_W1B : OFF_W0);
        uint32_t whb[4];
        #pragma unroll
        for (int jp = 0; jp < 4; jp++) whb[jp] = wb + rowB[jp] * 256;

        #pragma unroll
        for (int ks = 0; ks < 8; ks++) {
            const int kq = ks * 2;
            uint32_t a0, a1, a2, a3, l0, l1, l2, l3;
            const uint32_t ao = (uint32_t)((kq + kuA) ^ rxA) << 4;
            ldsm4(a0, a1, a2, a3, ahb + ao);
            ldsm4(l0, l1, l2, l3, alb + ao);
            uint32_t bh[16];
            #pragma unroll
            for (int jp = 0; jp < 4; jp++) {
                const uint32_t bo = (uint32_t)((kq + kuB) ^ rxB[jp]) << 4;
                ldsm4(bh[4*jp], bh[4*jp+1], bh[4*jp+2], bh[4*jp+3], whb[jp] + bo);
            }
            #pragma unroll
            for (int j = 0; j < 8; j++)
                mma16816(&acc[4*j], a0, a1, a2, a3, bh[2*j], bh[2*j+1]);
            #pragma unroll
            for (int j = 0; j < 8; j++)
                mma16816(&acc[4*j], l0, l1, l2, l3, bh[2*j], bh[2*j+1]);
        }
    }

    // ---- epilogue1: h1 = relu(C1 + b1) -> fp16 hi/lo into A23 planes ----
    __syncthreads();   // GEMM1 reads of A23 complete
    {
        const int r1 = m0 + (lane >> 2);
        #pragma unroll
        for (int j = 0; j < 8; j++) {
            const int col = wn * 64 + j * 8 + (lane & 3) * 2;
            const float ba = __ldg(b1 + col), bb = __ldg(b1 + col + 1);
            float v00 = fmaxf(acc[4*j]   + ba, 0.0f);
            float v01 = fmaxf(acc[4*j+1] + bb, 0.0f);
            float v10 = fmaxf(acc[4*j+2] + ba, 0.0f);
            float v11 = fmaxf(acc[4*j+3] + bb, 0.0f);
            uint16_t h0, h1v, l0v, l1v;
            const uint32_t o1 = aoff(r1, col), o2 = aoff(r1 + 8, col);
            hsplit(v00, h0, l0v); hsplit(v01, h1v, l1v);
            *(uint32_t*)(sm + OFF_A23_H + o1) = (uint32_t)h0 | ((uint32_t)h1v << 16);
            *(uint32_t*)(sm + OFF_A23_L + o1) = (uint32_t)l0v | ((uint32_t)l1v << 16);
            hsplit(v10, h0, l0v); hsplit(v11, h1v, l1v);
            *(uint32_t*)(sm + OFF_A23_H + o2) = (uint32_t)h0 | ((uint32_t)h1v << 16);
            *(uint32_t*)(sm + OFF_A23_L + o2) = (uint32_t)l0v | ((uint32_t)l1v << 16);
        }
    }
    cp_wait<0>();       // W2 resident
    __syncthreads();

    // ---- GEMM2: C2[64][64] = h1 @ W2 ----
    float acc2[16];
    #pragma unroll
    for (int i = 0; i < 16; i++) acc2[i] = 0.0f;
    {
        const uint32_t ahb = smb + OFF_A23_H + rowA * 256;
        const uint32_t alb = smb + OFF_A23_L + rowA * 256;
        int rowB2[2], rxB2[2];
        #pragma unroll
        for (int jp = 0; jp < 2; jp++) {
            rowB2[jp] = wn * 32 + jp * 16 + ((lane >> 4) << 3) + (lane & 7);
            rxB2[jp]  = rowB2[jp] & 7;
        }
        #pragma unroll
        for (int ks = 0; ks < 8; ks++) {
            const int kq = ks * 2;
            uint32_t a0, a1, a2, a3, l0, l1, l2, l3;
            const uint32_t ao = (uint32_t)((kq + kuA) ^ rxA) << 4;
            ldsm4(a0, a1, a2, a3, ahb + ao);
            ldsm4(l0, l1, l2, l3, alb + ao);
            uint32_t bh[8];
            #pragma unroll
            for (int jp = 0; jp < 2; jp++) {
                const uint32_t wbase = smb + OFF_W0 + rowB2[jp] * 256;
                const uint32_t bo = (uint32_t)((kq + kuB) ^ rxB2[jp]) << 4;
                ldsm4(bh[4*jp], bh[4*jp+1], bh[4*jp+2], bh[4*jp+3], wbase + bo);
            }
            #pragma unroll
            for (int j = 0; j < 4; j++)
                mma16816(&acc2[4*j], a0, a1, a2, a3, bh[2*j], bh[2*j+1]);
            #pragma unroll
            for (int j = 0; j < 4; j++)
                mma16816(&acc2[4*j], l0, l1, l2, l3, bh[2*j], bh[2*j+1]);
        }
    }

    // ---- epilogue2: score = relu(C2 + b2) . W3 (+b3) ----
    {
        float p1 = 0.0f, p2 = 0.0f;
        #pragma unroll
        for (int j = 0; j < 4; j++) {
            const int col = wn * 32 + j * 8 + (lane & 3) * 2;
            const float ba = __ldg(b2 + col), bb = __ldg(b2 + col + 1);
            const float wa = __ldg(W3 + col), wwb = __ldg(W3 + col + 1);
            p1 += fmaxf(acc2[4*j]   + ba, 0.0f) * wa;
            p1 += fmaxf(acc2[4*j+1] + bb, 0.0f) * wwb;
            p2 += fmaxf(acc2[4*j+2] + ba, 0.0f) * wa;
            p2 += fmaxf(acc2[4*j+3] + bb, 0.0f) * wwb;
        }
        p1 += __shfl_xor_sync(0xffffffff, p1, 1);
        p1 += __shfl_xor_sync(0xffffffff, p1, 2);
        p2 += __shfl_xor_sync(0xffffffff, p2, 1);
        p2 += __shfl_xor_sync(0xffffffff, p2, 2);
        float* part = (float*)(sm + OFF_PART);
        if ((lane & 3) == 0) {
            const int r1 = m0 + (lane >> 2);
            part[wn * 64 + r1]     = p1;
            part[wn * 64 + r1 + 8] = p2;
        }
    }
    __syncthreads();
    if (tid < MB) {
        const float* part = (const float*)(sm + OFF_PART);
        const int e = eb + tid;
        if (e < E) out[e] = part[tid] + part[64 + tid] + __ldg(b3);
    }
}

// ---- launcher ----
extern "C" void kernel_launch(void* const* d_in, const int* in_sizes, int n_in,
                              void* d_out, int out_size)
{
    const float* z  = (const float*)d_in[0];
    const void*  ei = d_in[1];
    const float* W1 = (const float*)d_in[2];
    const float* b1 = (const float*)d_in[3];
    const float* W2 = (const float*)d_in[4];
    const float* b2 = (const float*)d_in[5];
    const float* W3 = (const float*)d_in[6];
    const float* b3 = (const float*)d_in[7];
    float* out = (float*)d_out;

    const int E = out_size;
    const int n_nodes = in_sizes[0] / HDIM;

    static bool attr_set = false;
    if (!attr_set) {
        cudaFuncSetAttribute(lp_main, cudaFuncAttributeMaxDynamicSharedMemorySize, SMEM_TOTAL);
        attr_set = true;
    }

    detect_ei_dtype<<<1, 1>>>(ei, E, n_nodes);
    prep_weights<<<288, 256>>>(W1, W2);

    const int grid = (E + MB - 1) / MB;
    lp_main<<<grid, THREADS, SMEM_TOTAL>>>(z, ei, b1, b2, W3, b3, out, E);
}

// round 7
// speedup vs baseline: 5.7400x; 2.1969x over previous
#include <cuda_runtime.h>
#include <cuda_fp16.h>
#include <cstdint>
#include <math.h>

// LinkPredictor via mma.sync (HMMA fp16 single-pass, fp32 accum), 2 CTAs/SM.
// Valid at compute_103. Error ~4.6e-4 (A + W fp16 truncation) < 1e-3.
// Inputs: 0:z[500000*128]f32 1:edge_index[2*E] (i32 or i64)
//         2:W1[512*128] 3:b1[128] 4:W2[128*64] 5:b2[64] 6:W3[64] 7:b3[1]
// Output: score[E] f32

#define HDIM 128
constexpr int MB      = 64;     // edges per block
constexpr int THREADS = 256;    // 8 warps

// ---- smem layout (bytes) ----
constexpr int OFF_PART = 0;         // 512 B reduction scratch
constexpr int PLANE    = 16384;     // 64 rows * 256 B
constexpr int OFF_SRC  = 512;
constexpr int OFF_DST  = OFF_SRC + PLANE;   // 16896
constexpr int OFF_A23  = OFF_DST + PLANE;   // 33280 (chunk2/3, later h1)
constexpr int OFF_W0   = OFF_A23 + PLANE;   // 49664 (32 KB buf)
constexpr int OFF_W1B  = OFF_W0 + 32768;    // 82432 (32 KB buf)
constexpr int SMEM_TOTAL = OFF_W1B + 32768; // 115200  -> 2 CTAs/SM

// preconverted, pre-swizzled weights (single fp16)
__device__ unsigned char g_W1p[4 * 32768];  // [chunk][n=128 rows][k=128 fp16]
__device__ unsigned char g_W2p[16384];      // [n=64 rows][k=128 fp16]
__device__ int g_ei_is64;

// ---- helpers ----
__device__ __forceinline__ uint32_t smem_u32(const void* p) {
    uint32_t a;
    asm("{ .reg .u64 t; cvta.to.shared.u64 t, %1; cvt.u32.u64 %0, t; }" : "=r"(a) : "l"(p));
    return a;
}
__device__ __forceinline__ void ldsm4(uint32_t& r0, uint32_t& r1, uint32_t& r2, uint32_t& r3,
                                      uint32_t addr) {
    asm volatile("ldmatrix.sync.aligned.m8n8.x4.shared.b16 {%0,%1,%2,%3}, [%4];"
        : "=r"(r0), "=r"(r1), "=r"(r2), "=r"(r3) : "r"(addr));
}
__device__ __forceinline__ void mma16816(float* c, uint32_t a0, uint32_t a1, uint32_t a2,
                                         uint32_t a3, uint32_t b0, uint32_t b1) {
    asm volatile("mma.sync.aligned.m16n8k16.row.col.f32.f16.f16.f32 "
        "{%0,%1,%2,%3}, {%4,%5,%6,%7}, {%8,%9}, {%0,%1,%2,%3};"
        : "+f"(c[0]), "+f"(c[1]), "+f"(c[2]), "+f"(c[3])
        : "r"(a0), "r"(a1), "r"(a2), "r"(a3), "r"(b0), "r"(b1));
}
__device__ __forceinline__ void cp16(uint32_t dst, const void* src) {
    asm volatile("cp.async.cg.shared.global [%0], [%1], 16;" :: "r"(dst), "l"(src));
}
#define CP_COMMIT() asm volatile("cp.async.commit_group;" ::: "memory")
template <int N> __device__ __forceinline__ void cp_wait() {
    asm volatile("cp.async.wait_group %0;" :: "n"(N) : "memory");
}

// swizzled offset within a plane: row stride 256B, 16B units XORed by row&7
__device__ __host__ __forceinline__ uint32_t aoff(int row, int k) {
    return (uint32_t)(row * 256 + (((k >> 3) ^ (row & 7)) << 4) + (k & 7) * 2);
}
__device__ __forceinline__ uint2 pack4h(float4 v) {
    uint2 r;
    __half2 p0 = __floats2half2_rn(v.x, v.y);
    __half2 p1 = __floats2half2_rn(v.z, v.w);
    r.x = *(uint32_t*)&p0;
    r.y = *(uint32_t*)&p1;
    return r;
}
__device__ __forceinline__ float hfr(uint32_t w, int hi16) {
    return __half2float(__ushort_as_half((uint16_t)(hi16 ? (w >> 16) : (w & 0xffff))));
}

// ---- setup kernels ----
__global__ void detect_ei_dtype(const void* ei, int E, int n_nodes) {
    const long long* e64 = (const long long*)ei;
    int n = (E < 64) ? E : 64;
    int is64 = 1;
    for (int i = 0; i < n; i++) {
        long long v = e64[i];
        if (v < 0 || v >= (long long)n_nodes) { is64 = 0; break; }
    }
    g_ei_is64 = is64;
}

__global__ void prep_weights(const float* __restrict__ W1, const float* __restrict__ W2) {
    int idx = blockIdx.x * 256 + threadIdx.x;
    if (idx < 65536) {                       // W1[512][128]: B[n][k] = W1[c*128+k][n]
        int c = idx >> 14, e = idx & 16383;
        int n = e >> 7, k = e & 127;
        float f = W1[(c * 128 + k) * 128 + n];
        *(uint16_t*)(g_W1p + (size_t)c * 32768 + aoff(n, k)) =
            __half_as_ushort(__float2half_rn(f));
    } else if (idx < 65536 + 8192) {         // W2[128][64]: B[n][k] = W2[k][n]
        int e = idx - 65536;
        int n = e >> 7, k = e & 127;
        *(uint16_t*)(g_W2p + aoff(n, k)) =
            __half_as_ushort(__float2half_rn(W2[k * 64 + n]));
    }
}

// ---- main kernel ----
__global__ __launch_bounds__(THREADS, 2)
void lp_main(const float* __restrict__ z,
             const void* __restrict__ ei_raw,
             const float* __restrict__ b1,
             const float* __restrict__ b2,
             const float* __restrict__ W3,
             const float* __restrict__ b3,
             float* __restrict__ out,
             int E)
{
    extern __shared__ unsigned char sm[];
    const uint32_t smb = smem_u32(sm);
    const int tid  = threadIdx.x;
    const int warp = tid >> 5;
    const int lane = tid & 31;
    const int wm = warp >> 1, wn = warp & 1;
    const int m0 = wm * 16;
    const int eb = blockIdx.x * MB;

    // prefetch W1 chunk 0 -> wbuf0 (32 KB)
    {
        #pragma unroll
        for (int t = 0; t < 8; t++) {
            uint32_t o = (uint32_t)(tid + t * 256) * 16;
            cp16(smb + OFF_W0 + o, g_W1p + o);
        }
        CP_COMMIT();
    }

    // ---- gather: build src/dst fp16 planes + chunk2 (src*dst) ----
    {
        const int is64 = g_ei_is64;
        const long long* e64 = (const long long*)ei_raw;
        const int*       e32 = (const int*)ei_raw;
        #pragma unroll 2
        for (int i = 0; i < 8; i++) {
            const int r = warp * 8 + i;
            const int e = eb + r;
            const int ec = (e < E) ? e : (E - 1);
            long long s, d;
            if (is64) { s = e64[ec]; d = e64[(size_t)E + ec]; }
            else      { s = (long long)e32[ec]; d = (long long)e32[(size_t)E + ec]; }

            const float4 sv = *(const float4*)(z + (size_t)s * HDIM + lane * 4);
            const float4 dv = *(const float4*)(z + (size_t)d * HDIM + lane * 4);
            float4 iv;
            iv.x = sv.x * dv.x; iv.y = sv.y * dv.y; iv.z = sv.z * dv.z; iv.w = sv.w * dv.w;

            const uint32_t o = aoff(r, lane * 4);
            *(uint2*)(sm + OFF_SRC + o) = pack4h(sv);
            *(uint2*)(sm + OFF_DST + o) = pack4h(dv);
            *(uint2*)(sm + OFF_A23 + o) = pack4h(iv);
        }
    }

    // ---- per-thread ldmatrix geometry ----
    const int tileA = lane >> 3;
    const int rowA  = m0 + ((tileA & 1) << 3) + (lane & 7);
    const int rxA   = rowA & 7;
    const int kuA   = tileA >> 1;            // 0 or 1 (k unit offset)
    const int kuB   = (lane >> 3) & 1;
    int rowB[4], rxB[4];
    {
        const int nb = wn * 64;
        #pragma unroll
        for (int jp = 0; jp < 4; jp++) {
            rowB[jp] = nb + jp * 16 + ((lane >> 4) << 3) + (lane & 7);
            rxB[jp]  = rowB[jp] & 7;
        }
    }

    float acc[32];
    #pragma unroll
    for (int i = 0; i < 32; i++) acc[i] = 0.0f;

    static const int AOFS[4] = {OFF_SRC, OFF_DST, OFF_A23, OFF_A23};

    // ---- GEMM1: 4 K-chunks of 128 ----
    #pragma unroll 1
    for (int c = 0; c < 4; c++) {
        __syncthreads();     // prev chunk's smem reads complete

        if (c == 3) {        // rebuild A23 = |src-dst| from fp16 planes
            #pragma unroll
            for (int t = 0; t < 4; t++) {
                const int idx = tid + t * 256;      // 1024 items of 8 cols
                const int r = idx >> 4, kg = (idx & 15) * 8;
                const uint32_t o = aoff(r, kg);
                const uint4 shv = *(const uint4*)(sm + OFF_SRC + o);
                const uint4 dhv = *(const uint4*)(sm + OFF_DST + o);
                uint4 rv;
                const uint32_t* sp = &shv.x;
                const uint32_t* dp = &dhv.x;
                uint32_t* rp = &rv.x;
                #pragma unroll
                for (int q = 0; q < 4; q++) {
                    float a0 = fabsf(hfr(sp[q],0) - hfr(dp[q],0));
                    float a1 = fabsf(hfr(sp[q],1) - hfr(dp[q],1));
                    __half2 p = __floats2half2_rn(a0, a1);
                    rp[q] = *(uint32_t*)&p;
                }
                *(uint4*)(sm + OFF_A23 + o) = rv;
            }
        }

        // prefetch next W block into the other buffer
        if (c < 3) {
            const unsigned char* src = g_W1p + (size_t)(c + 1) * 32768;
            const uint32_t dst = smb + (((c + 1) & 1) ? OFF_W1B : OFF_W0);
            #pragma unroll
            for (int t = 0; t < 8; t++) {
                uint32_t o = (uint32_t)(tid + t * 256) * 16;
                cp16(dst + o, src + o);
            }
        } else {
            #pragma unroll
            for (int t = 0; t < 4; t++) {
                uint32_t o = (uint32_t)(tid + t * 256) * 16;
                cp16(smb + OFF_W0 + o, g_W2p + o);
            }
        }
        CP_COMMIT();
        cp_wait<1>();        // current chunk's W resident
        __syncthreads();

        const uint32_t ab = smb + AOFS[c] + rowA * 256;
        const uint32_t wb = smb + ((c & 1) ? OFF_W1B : OFF_W0);
        uint32_t whb[4];
        #pragma unroll
        for (int jp = 0; jp < 4; jp++) whb[jp] = wb + rowB[jp] * 256;

        #pragma unroll
        for (int ks = 0; ks < 8; ks++) {
            const int kq = ks * 2;
            uint32_t a0, a1, a2, a3;
            const uint32_t ao = (uint32_t)((kq + kuA) ^ rxA) << 4;
            ldsm4(a0, a1, a2, a3, ab + ao);
            uint32_t bh[16];
            #pragma unroll
            for (int jp = 0; jp < 4; jp++) {
                const uint32_t bo = (uint32_t)((kq + kuB) ^ rxB[jp]) << 4;
                ldsm4(bh[4*jp], bh[4*jp+1], bh[4*jp+2], bh[4*jp+3], whb[jp] + bo);
            }
            #pragma unroll
            for (int j = 0; j < 8; j++)
                mma16816(&acc[4*j], a0, a1, a2, a3, bh[2*j], bh[2*j+1]);
        }
    }

    // ---- epilogue1: h1 = relu(C1 + b1) -> fp16 into A23 plane ----
    __syncthreads();   // GEMM1 reads of A23 complete
    {
        const int r1 = m0 + (lane >> 2);
        #pragma unroll
        for (int j = 0; j < 8; j++) {
            const int col = wn * 64 + j * 8 + (lane & 3) * 2;
            const float ba = __ldg(b1 + col), bb = __ldg(b1 + col + 1);
            __half2 p0 = __floats2half2_rn(fmaxf(acc[4*j]   + ba, 0.0f),
                                           fmaxf(acc[4*j+1] + bb, 0.0f));
            __half2 p1 = __floats2half2_rn(fmaxf(acc[4*j+2] + ba, 0.0f),
                                           fmaxf(acc[4*j+3] + bb, 0.0f));
            *(uint32_t*)(sm + OFF_A23 + aoff(r1, col))     = *(uint32_t*)&p0;
            *(uint32_t*)(sm + OFF_A23 + aoff(r1 + 8, col)) = *(uint32_t*)&p1;
        }
    }
    cp_wait<0>();       // W2 resident
    __syncthreads();

    // ---- GEMM2: C2[64][64] = h1 @ W2 ----
    float acc2[16];
    #pragma unroll
    for (int i = 0; i < 16; i++) acc2[i] = 0.0f;
    {
        const uint32_t ab = smb + OFF_A23 + rowA * 256;
        int rowB2[2], rxB2[2];
        #pragma unroll
        for (int jp = 0; jp < 2; jp++) {
            rowB2[jp] = wn * 32 + jp * 16 + ((lane >> 4) << 3) + (lane & 7);
            rxB2[jp]  = rowB2[jp] & 7;
        }
        #pragma unroll
        for (int ks = 0; ks < 8; ks++) {
            const int kq = ks * 2;
            uint32_t a0, a1, a2, a3;
            const uint32_t ao = (uint32_t)((kq + kuA) ^ rxA) << 4;
            ldsm4(a0, a1, a2, a3, ab + ao);
            uint32_t bh[8];
            #pragma unroll
            for (int jp = 0; jp < 2; jp++) {
                const uint32_t wbase = smb + OFF_W0 + rowB2[jp] * 256;
                const uint32_t bo = (uint32_t)((kq + kuB) ^ rxB2[jp]) << 4;
                ldsm4(bh[4*jp], bh[4*jp+1], bh[4*jp+2], bh[4*jp+3], wbase + bo);
            }
            #pragma unroll
            for (int j = 0; j < 4; j++)
                mma16816(&acc2[4*j], a0, a1, a2, a3, bh[2*j], bh[2*j+1]);
        }
    }

    // ---- epilogue2: score = relu(C2 + b2) . W3 (+b3) ----
    {
        float p1 = 0.0f, p2 = 0.0f;
        #pragma unroll
        for (int j = 0; j < 4; j++) {
            const int col = wn * 32 + j * 8 + (lane & 3) * 2;
            const float ba = __ldg(b2 + col), bb = __ldg(b2 + col + 1);
            const float wa = __ldg(W3 + col), wwb = __ldg(W3 + col + 1);
            p1 += fmaxf(acc2[4*j]   + ba, 0.0f) * wa;
            p1 += fmaxf(acc2[4*j+1] + bb, 0.0f) * wwb;
            p2 += fmaxf(acc2[4*j+2] + ba, 0.0f) * wa;
            p2 += fmaxf(acc2[4*j+3] + bb, 0.0f) * wwb;
        }
        p1 += __shfl_xor_sync(0xffffffff, p1, 1);
        p1 += __shfl_xor_sync(0xffffffff, p1, 2);
        p2 += __shfl_xor_sync(0xffffffff, p2, 1);
        p2 += __shfl_xor_sync(0xffffffff, p2, 2);
        float* part = (float*)(sm + OFF_PART);
        if ((lane & 3) == 0) {
            const int r1 = m0 + (lane >> 2);
            part[wn * 64 + r1]     = p1;
            part[wn * 64 + r1 + 8] = p2;
        }
    }
    __syncthreads();
    if (tid < MB) {
        const float* part = (const float*)(sm + OFF_PART);
        const int e = eb + tid;
        if (e < E) out[e] = part[tid] + part[64 + tid] + __ldg(b3);
    }
}

// ---- launcher ----
extern "C" void kernel_launch(void* const* d_in, const int* in_sizes, int n_in,
                              void* d_out, int out_size)
{
    const float* z  = (const float*)d_in[0];
    const void*  ei = d_in[1];
    const float* W1 = (const float*)d_in[2];
    const float* b1 = (const float*)d_in[3];
    const float* W2 = (const float*)d_in[4];
    const float* b2 = (const float*)d_in[5];
    const float* W3 = (const float*)d_in[6];
    const float* b3 = (const float*)d_in[7];
    float* out = (float*)d_out;

    const int E = out_size;
    const int n_nodes = in_sizes[0] / HDIM;

    static bool attr_set = false;
    if (!attr_set) {
        cudaFuncSetAttribute(lp_main, cudaFuncAttributeMaxDynamicSharedMemorySize, SMEM_TOTAL);
        attr_set = true;
    }

    detect_ei_dtype<<<1, 1>>>(ei, E, n_nodes);
    prep_weights<<<288, 256>>>(W1, W2);

    const int grid = (E + MB - 1) / MB;
    lp_main<<<grid, THREADS, SMEM_TOTAL>>>(z, ei, b1, b2, W3, b3, out, E);
}